// round 14
// baseline (speedup 1.0000x reference)
#include <cuda_runtime.h>
#include <cstdint>
#include <cstddef>

#define NEGV (-1e30f)

static const int Bn = 128;
static const int Tn = 2048;
static const int Nn = 64;
static const int Ln = 256;

// result scratch + combine flags (device globals: allocation-free)
__device__ float g_fcc[Bn];
__device__ float g_fac[Bn];
__device__ unsigned g_flag[Bn];   // monotonic; parity selects per-call 2nd arriver

// ---------------------------------------------------------------------------
// Packed f32x2 helpers (Blackwell: fma.rn.f32x2 only reachable via PTX)
// ---------------------------------------------------------------------------
__device__ __forceinline__ void fma2(unsigned long long& acc,
                                     unsigned long long e,
                                     unsigned long long w) {
    asm("fma.rn.f32x2 %0, %1, %2, %0;" : "+l"(acc) : "l"(e), "l"(w));
}
__device__ __forceinline__ unsigned long long add2(unsigned long long a,
                                                   unsigned long long b) {
    unsigned long long r;
    asm("add.rn.f32x2 %0, %1, %2;" : "=l"(r) : "l"(a), "l"(b));
    return r;
}
__device__ __forceinline__ void cp4(void* dst, const void* src) {
    unsigned int d = (unsigned int)__cvta_generic_to_shared(dst);
    asm volatile("cp.async.ca.shared.global [%0], [%1], 4;" :: "r"(d), "l"(src) : "memory");
}
#define CP_COMMIT() asm volatile("cp.async.commit_group;" ::: "memory")
#define CP_WAIT5()  asm volatile("cp.async.wait_group 5;" ::: "memory")

// ---------------------------------------------------------------------------
// Single kernel, grid 256 x 128 threads — the R5 (288.5us) structure.
//   blocks   0..127 : fcc for batch b (64 live threads, thread = class n).
//       cp.async smem ring for x_t (distance 6), smem E exchange, ONE
//       __syncthreads per step. Tail uses the EXACT power-of-2 renorm
//       (integer exponent strip of E_prev[0]); exp(x_{t+1}) is computed
//       off-chain AFTER this step's CP_WAIT5 (which completes slot t+1).
//   blocks 128..255 : fac for batch b (128 threads, thread = 2 target lanes,
//       R5 smem staging verbatim).
// The (fcc b, fac b) pair's 2nd finisher writes out[b] (parity atomic).
// ---------------------------------------------------------------------------
__global__ void __launch_bounds__(128, 1) asg_main(
    const float* __restrict__ xin_all, const int* __restrict__ tgt_all,
    const int* __restrict__ tsz_all, const float* __restrict__ trans,
    float* __restrict__ out)
{
    __shared__ __align__(16) float sx[8][64];     // x_t staging ring
    __shared__ __align__(16) float sE[2][64];     // fcc state, double buffered
    __shared__ float sfb[2][4];                   // fac warp-boundary, dbl buf

    const int role = blockIdx.x >> 7;             // 0: fcc, 1: fac
    const int b = blockIdx.x & 127;
    const int tid = threadIdx.x;
    const float* xin = xin_all + (size_t)b * Tn * Nn;

    if (role == 0) {
        // ================= fcc: scaled-exp forward scan ====================
        if (tid >= 64) return;                    // 2-warp CTA
        const int n = tid;

        unsigned long long w2[32];                // exp(trans[n, :]) packed
        const float* wr = trans + n * Nn;
#pragma unroll
        for (int j = 0; j < 32; j++) {
            float wa = __expf(wr[2 * j]);
            float wb = __expf(wr[2 * j + 1]);
            asm("mov.b64 %0, {%1, %2};" : "=l"(w2[j]) : "f"(wa), "f"(wb));
        }
        sE[0][n] = __expf(xin[n]);                // alpha0 = x0
        int iexp = 0;                             // sum of stripped exponents

        // prologue: stage x_t for t = 1..6
#pragma unroll
        for (int tt = 1; tt <= 6; tt++) {
            cp4(&sx[tt & 7][n], xin + (size_t)tt * Nn + n);
            CP_COMMIT();
        }
        CP_WAIT5();                               // completes slots 1,2
        float p_cur = __expf(sx[1][n]);           // exp(x[1])
        __syncthreads();

        for (int t = 1; t < Tn; ++t) {
            const int rb = (t + 1) & 1;           // E read buffer
            const int wbuf = t & 1;               // E write buffer

            float e0 = sE[rb][0];                 // scalar broadcast LDS
            const ulonglong2* ep = reinterpret_cast<const ulonglong2*>(sE[rb]);
            unsigned long long acc0 = 0ull, acc1 = 0ull, acc2 = 0ull, acc3 = 0ull;
#pragma unroll
            for (int k2 = 0; k2 < 16; k2++) {
                ulonglong2 e = ep[k2];            // broadcast LDS.128
                if (k2 & 1) {
                    fma2(acc2, e.x, w2[2 * k2]);
                    fma2(acc3, e.y, w2[2 * k2 + 1]);
                } else {
                    fma2(acc0, e.x, w2[2 * k2]);
                    fma2(acc1, e.y, w2[2 * k2 + 1]);
                }
            }
            unsigned long long s = add2(add2(acc0, acc1), add2(acc2, acc3));
            float slo, shi;
            asm("mov.b64 {%0, %1}, %2;" : "=f"(slo), "=f"(shi) : "l"(s));
            float S = slo + shi;

            // EXACT renorm: strip E_prev[0]'s exponent (uniform across threads)
            int k = ((__float_as_int(e0) >> 23) & 0xff) - 127;
            iexp += k;
            float En = S * p_cur;                 // p_cur precomputed last iter
            En = __int_as_float(__float_as_int(En) - (k << 23));  // * 2^-k
            sE[wbuf][n] = En;

            // ring maintenance for t+6; WAIT5 completes slot t+1, then the
            // off-chain pre-exp for next step reads it (formally ordered).
            int tpf = t + 6; if (tpf > Tn - 1) tpf = Tn - 1;
            cp4(&sx[(t + 6) & 7][n], xin + (size_t)tpf * Nn + n);
            CP_COMMIT();
            CP_WAIT5();
            if (t + 1 < Tn) p_cur = __expf(sx[(t + 1) & 7][n]);
            __syncthreads();
        }

        // epilogue: fcc = iexp*ln2 + ln(sum_n E[n]); last buffer = 2047&1 = 1
        if (tid < 32) {
            float v = sE[1][tid] + sE[1][tid + 32];
#pragma unroll
            for (int o = 16; o > 0; o >>= 1)
                v += __shfl_xor_sync(0xffffffffu, v, o);
            if (tid == 0) {
                float fcc = (float)iexp * 0.69314718055994531f + __logf(v);
                g_fcc[b] = fcc;
                __threadfence();
                unsigned old = atomicAdd(&g_flag[b], 1u);
                if (old & 1u) {                   // 2nd arriver this call
                    __threadfence();
                    out[b] = fcc - g_fac[b];
                }
            }
        }
    } else {
        // ================= fac: log-domain constrained scan (R5 verbatim) ==
        const int f = tid;                        // 0..127, lanes 2f, 2f+1
        const int l0 = 2 * f, l1 = 2 * f + 1;
        const int tg0 = tgt_all[b * Ln + l0];
        const int tg1 = tgt_all[b * Ln + l1];
        const int tgm = (l0 > 0) ? tgt_all[b * Ln + l0 - 1] : 0;
        const float ts0 = trans[tg0 * Nn + tg0];
        const float ts1 = trans[tg1 * Nn + tg1];
        const float tm0 = trans[tg0 * Nn + tgm];  // move into l0 (unused if l0==0)
        const float tm1 = trans[tg1 * Nn + tg0];  // move into l1
        const int tssel = tsz_all[b];

        float a0 = (l0 == 0) ? xin[tg0] : NEGV;   // alpha0[0] = x0[target[0]]
        float a1 = NEGV;
        if ((f & 31) == 31) sfb[0][f >> 5] = a1;

        if (f < 64) {
#pragma unroll
            for (int tt = 1; tt <= 6; tt++) {
                cp4(&sx[tt & 7][f], xin + (size_t)tt * Nn + f);
                CP_COMMIT();
            }
            CP_WAIT5();
        }
        __syncthreads();

        for (int t = 1; t < Tn; ++t) {
            const int rs = t & 7;
            const int rb = (t + 1) & 1;
            const int wbuf = t & 1;

            float ap = __shfl_up_sync(0xffffffffu, a1, 1);
            float e0 = sx[rs][tg0];
            float e1 = sx[rs][tg1];
            if ((f & 31) == 0) ap = (f == 0) ? NEGV : sfb[rb][(f >> 5) - 1];

            float st1 = a1 + ts1, mv1 = a0 + tm1; // uses OLD a0
            float h1 = fmaxf(st1, mv1), lo1 = fminf(st1, mv1);
            float na1 = e1 + h1 + __logf(1.0f + __expf(lo1 - h1));

            float st0 = a0 + ts0, mv0 = ap + tm0;
            float h0 = fmaxf(st0, mv0), lo0 = fminf(st0, mv0);
            float na0 = e0 + h0 + __logf(1.0f + __expf(lo0 - h0));

            a0 = na0; a1 = na1;
            if ((f & 31) == 31) sfb[wbuf][f >> 5] = a1;

            if (f < 64) {
                int tpf = t + 6; if (tpf > Tn - 1) tpf = Tn - 1;
                cp4(&sx[(t + 6) & 7][f], xin + (size_t)tpf * Nn + f);
                CP_COMMIT();
                CP_WAIT5();
            }
            __syncthreads();
        }

        if (l0 == tssel - 1) g_fac[b] = a0;
        if (l1 == tssel - 1) g_fac[b] = a1;
        __syncthreads();
        if (tid == 0) {
            __threadfence();
            unsigned old = atomicAdd(&g_flag[b], 1u);
            if (old & 1u) {                       // 2nd arriver this call
                __threadfence();
                out[b] = g_fcc[b] - g_fac[b];
            }
        }
    }
}

// ---------------------------------------------------------------------------
extern "C" void kernel_launch(void* const* d_in, const int* in_sizes, int n_in,
                              void* d_out, int out_size) {
    const float* in    = (const float*)d_in[0];   // input  [B,T,N] f32
    const int*   tgt   = (const int*)  d_in[1];   // target [B,L]   i32
    const int*   tsz   = (const int*)  d_in[2];   // target_size [B]
    const float* trans = (const float*)d_in[3];   // trans  [N,N]   f32
    float* out = (float*)d_out;
    (void)in_sizes; (void)n_in; (void)out_size;

    asg_main<<<2 * Bn, 128>>>(in, tgt, tsz, trans, out);
}

// round 16
// speedup vs baseline: 1.1987x; 1.1987x over previous
#include <cuda_runtime.h>
#include <cstdint>
#include <cstddef>

#define NEGV (-1e30f)

static const int Bn = 128;
static const int Tn = 2048;
static const int Nn = 64;
static const int Ln = 256;

// result scratch + combine flags (device globals: allocation-free)
__device__ float g_fcc[Bn];
__device__ float g_fac[Bn];
__device__ unsigned g_flag[Bn];   // monotonic; parity selects per-call 2nd arriver

// ---------------------------------------------------------------------------
// Packed f32x2 helpers (Blackwell: fma.rn.f32x2 only reachable via PTX)
// ---------------------------------------------------------------------------
__device__ __forceinline__ void fma2(unsigned long long& acc,
                                     unsigned long long e,
                                     unsigned long long w) {
    asm("fma.rn.f32x2 %0, %1, %2, %0;" : "+l"(acc) : "l"(e), "l"(w));
}
__device__ __forceinline__ unsigned long long add2(unsigned long long a,
                                                   unsigned long long b) {
    unsigned long long r;
    asm("add.rn.f32x2 %0, %1, %2;" : "=l"(r) : "l"(a), "l"(b));
    return r;
}
__device__ __forceinline__ void cp4(void* dst, const void* src) {
    unsigned int d = (unsigned int)__cvta_generic_to_shared(dst);
    asm volatile("cp.async.ca.shared.global [%0], [%1], 4;" :: "r"(d), "l"(src) : "memory");
}
#define CP_COMMIT() asm volatile("cp.async.commit_group;" ::: "memory")
#define CP_WAIT5()  asm volatile("cp.async.wait_group 5;" ::: "memory")

// ---------------------------------------------------------------------------
// Single kernel, grid 256 x 128 threads — R5 dataflow restored exactly.
//   blocks   0..127 : fcc for batch b (64 live threads, thread = class n).
//       Step t: LDS xv + e0 early; px = __expf(xv) and the exponent strip of
//       e0 run IN PARALLEL with the 32-FFMA2 chain (this is the placement R5
//       had and R9/R10/R13/R14 broke by moving the exp into the step tail).
//       Tail after S is only FMUL + integer exponent adjust + STS.
//       cp.async ring distance 6, per-step WAIT5, ONE __syncthreads.
//   blocks 128..255 : fac for batch b (R5 verbatim: smem staging, 4 warps,
//       thread = 2 target lanes).
// The (fcc b, fac b) pair's 2nd finisher writes out[b] (parity atomic).
// ---------------------------------------------------------------------------
__global__ void __launch_bounds__(128, 1) asg_main(
    const float* __restrict__ xin_all, const int* __restrict__ tgt_all,
    const int* __restrict__ tsz_all, const float* __restrict__ trans,
    float* __restrict__ out)
{
    __shared__ __align__(16) float sx[8][64];     // x_t staging ring
    __shared__ __align__(16) float sE[2][64];     // fcc state, double buffered
    __shared__ float sfb[2][4];                   // fac warp-boundary, dbl buf

    const int role = blockIdx.x >> 7;             // 0: fcc, 1: fac
    const int b = blockIdx.x & 127;
    const int tid = threadIdx.x;
    const float* xin = xin_all + (size_t)b * Tn * Nn;

    if (role == 0) {
        // ================= fcc: scaled-exp forward scan ====================
        if (tid >= 64) return;                    // 2-warp CTA
        const int n = tid;

        unsigned long long w2[32];                // exp(trans[n, :]) packed
        const float* wr = trans + n * Nn;
#pragma unroll
        for (int j = 0; j < 32; j++) {
            float wa = __expf(wr[2 * j]);
            float wb = __expf(wr[2 * j + 1]);
            asm("mov.b64 %0, {%1, %2};" : "=l"(w2[j]) : "f"(wa), "f"(wb));
        }
        sE[0][n] = __expf(xin[n]);                // alpha0 = x0
        int iexp = 0;                             // sum of stripped exponents

        // prologue: stage x_t for t = 1..6
#pragma unroll
        for (int tt = 1; tt <= 6; tt++) {
            cp4(&sx[tt & 7][n], xin + (size_t)tt * Nn + n);
            CP_COMMIT();
        }
        CP_WAIT5();
        __syncthreads();

        for (int t = 1; t < Tn; ++t) {
            const int rs = t & 7;
            const int rb = (t + 1) & 1;           // E read buffer
            const int wbuf = t & 1;               // E write buffer

            // ---- loads + off-chain work, all parallel to the FMA chain ----
            float e0 = sE[rb][0];                 // scalar broadcast LDS
            float xv = sx[rs][n];                 // this step's emission
            float px = __expf(xv);                // MUFU, independent of S
            int k = ((__float_as_int(e0) >> 23) & 0xff) - 127;  // ALU, parallel
            iexp += k;

            const ulonglong2* ep = reinterpret_cast<const ulonglong2*>(sE[rb]);
            unsigned long long acc0 = 0ull, acc1 = 0ull, acc2 = 0ull, acc3 = 0ull;
#pragma unroll
            for (int k2 = 0; k2 < 16; k2++) {
                ulonglong2 e = ep[k2];            // broadcast LDS.128
                if (k2 & 1) {
                    fma2(acc2, e.x, w2[2 * k2]);
                    fma2(acc3, e.y, w2[2 * k2 + 1]);
                } else {
                    fma2(acc0, e.x, w2[2 * k2]);
                    fma2(acc1, e.y, w2[2 * k2 + 1]);
                }
            }
            unsigned long long s = add2(add2(acc0, acc1), add2(acc2, acc3));
            float slo, shi;
            asm("mov.b64 {%0, %1}, %2;" : "=f"(slo), "=f"(shi) : "l"(s));
            float S = slo + shi;

            // ---- tail: FMUL + integer exponent adjust + STS only ----
            float En = S * px;                    // E' = S * exp(x) * 2^-k
            En = __int_as_float(__float_as_int(En) - (k << 23));
            sE[wbuf][n] = En;

            int tpf = t + 6; if (tpf > Tn - 1) tpf = Tn - 1;
            cp4(&sx[(t + 6) & 7][n], xin + (size_t)tpf * Nn + n);
            CP_COMMIT();
            CP_WAIT5();
            __syncthreads();
        }

        // epilogue: fcc = iexp*ln2 + ln(sum_n E[n]); last buffer = 2047&1 = 1
        if (tid < 32) {
            float v = sE[1][tid] + sE[1][tid + 32];
#pragma unroll
            for (int o = 16; o > 0; o >>= 1)
                v += __shfl_xor_sync(0xffffffffu, v, o);
            if (tid == 0) {
                float fcc = (float)iexp * 0.69314718055994531f + __logf(v);
                g_fcc[b] = fcc;
                __threadfence();
                unsigned old = atomicAdd(&g_flag[b], 1u);
                if (old & 1u) {                   // 2nd arriver this call
                    __threadfence();
                    out[b] = fcc - g_fac[b];
                }
            }
        }
    } else {
        // ================= fac: log-domain constrained scan (R5 verbatim) ==
        const int f = tid;                        // 0..127, lanes 2f, 2f+1
        const int l0 = 2 * f, l1 = 2 * f + 1;
        const int tg0 = tgt_all[b * Ln + l0];
        const int tg1 = tgt_all[b * Ln + l1];
        const int tgm = (l0 > 0) ? tgt_all[b * Ln + l0 - 1] : 0;
        const float ts0 = trans[tg0 * Nn + tg0];
        const float ts1 = trans[tg1 * Nn + tg1];
        const float tm0 = trans[tg0 * Nn + tgm];  // move into l0 (unused if l0==0)
        const float tm1 = trans[tg1 * Nn + tg0];  // move into l1
        const int tssel = tsz_all[b];

        float a0 = (l0 == 0) ? xin[tg0] : NEGV;   // alpha0[0] = x0[target[0]]
        float a1 = NEGV;
        if ((f & 31) == 31) sfb[0][f >> 5] = a1;

        if (f < 64) {
#pragma unroll
            for (int tt = 1; tt <= 6; tt++) {
                cp4(&sx[tt & 7][f], xin + (size_t)tt * Nn + f);
                CP_COMMIT();
            }
            CP_WAIT5();
        }
        __syncthreads();

        for (int t = 1; t < Tn; ++t) {
            const int rs = t & 7;
            const int rb = (t + 1) & 1;
            const int wbuf = t & 1;

            float ap = __shfl_up_sync(0xffffffffu, a1, 1);
            float e0 = sx[rs][tg0];
            float e1 = sx[rs][tg1];
            if ((f & 31) == 0) ap = (f == 0) ? NEGV : sfb[rb][(f >> 5) - 1];

            float st1 = a1 + ts1, mv1 = a0 + tm1; // uses OLD a0
            float h1 = fmaxf(st1, mv1), lo1 = fminf(st1, mv1);
            float na1 = e1 + h1 + __logf(1.0f + __expf(lo1 - h1));

            float st0 = a0 + ts0, mv0 = ap + tm0;
            float h0 = fmaxf(st0, mv0), lo0 = fminf(st0, mv0);
            float na0 = e0 + h0 + __logf(1.0f + __expf(lo0 - h0));

            a0 = na0; a1 = na1;
            if ((f & 31) == 31) sfb[wbuf][f >> 5] = a1;

            if (f < 64) {
                int tpf = t + 6; if (tpf > Tn - 1) tpf = Tn - 1;
                cp4(&sx[(t + 6) & 7][f], xin + (size_t)tpf * Nn + f);
                CP_COMMIT();
                CP_WAIT5();
            }
            __syncthreads();
        }

        if (l0 == tssel - 1) g_fac[b] = a0;
        if (l1 == tssel - 1) g_fac[b] = a1;
        __syncthreads();
        if (tid == 0) {
            __threadfence();
            unsigned old = atomicAdd(&g_flag[b], 1u);
            if (old & 1u) {                       // 2nd arriver this call
                __threadfence();
                out[b] = g_fcc[b] - g_fac[b];
            }
        }
    }
}

// ---------------------------------------------------------------------------
extern "C" void kernel_launch(void* const* d_in, const int* in_sizes, int n_in,
                              void* d_out, int out_size) {
    const float* in    = (const float*)d_in[0];   // input  [B,T,N] f32
    const int*   tgt   = (const int*)  d_in[1];   // target [B,L]   i32
    const int*   tsz   = (const int*)  d_in[2];   // target_size [B]
    const float* trans = (const float*)d_in[3];   // trans  [N,N]   f32
    float* out = (float*)d_out;
    (void)in_sizes; (void)n_in; (void)out_size;

    asg_main<<<2 * Bn, 128>>>(in, tgt, tsz, trans, out);
}